// round 15
// baseline (speedup 1.0000x reference)
#include <cuda_runtime.h>
#include <math.h>

// B=32, J=16, L=4096, MU_P=0.15, MASK_ID=103
#define ROW_LEN   4096
#define THREADS   512
#define EPT       8
#define MASK_ID_F 103.0f
#define FULLMASK  0xFFFFFFFFu

__global__ void __launch_bounds__(THREADS, 4)
gumbel_topk_mask_kernel(const int*   __restrict__ ids,
                        const float* __restrict__ msk2,   // (rows, 2*L)
                        const float* __restrict__ uu,     // (rows, L)
                        float*       __restrict__ out,    // (3, rows, L)
                        int N)
{
    __shared__ unsigned int hist[4][256];   // one per radix pass, cleared once
    __shared__ int          s_warpsum[16];
    __shared__ unsigned int s_prefix;
    __shared__ int          s_kk;

    const int t    = threadIdx.x;
    const int lane = t & 31;
    const int warp = t >> 5;
    const int row  = blockIdx.x;
    const int base = row * ROW_LEN;          // fits int

    const float* wrow = msk2 + row * (2 * ROW_LEN);
    const float* urow = uu   + base;
    const int*   irow = ids  + base;

    // Clear all 4 histograms once (1024 words, 2 per thread)
    ((unsigned int*)hist)[t]           = 0u;
    ((unsigned int*)hist)[t + THREADS] = 0u;

    // ---- Phase 1: build sortable keys.
    // order(score) == order( max(w,1e-30) / (-log u) ); r>0 so
    // bits(r)|0x80000000 is order-preserving. key==0 marks excluded (w<=0).
    unsigned int mykeys[EPT];
    #pragma unroll
    for (int g = 0; g < 2; g++) {
        float4 w4 = reinterpret_cast<const float4*>(wrow)[t * 2 + g];
        float4 u4 = reinterpret_cast<const float4*>(urow)[t * 2 + g];
        #pragma unroll
        for (int j = 0; j < 4; j++) {
            float w = (j == 0) ? w4.x : (j == 1) ? w4.y : (j == 2) ? w4.z : w4.w;
            float u = (j == 0) ? u4.x : (j == 1) ? u4.y : (j == 2) ? u4.z : u4.w;
            unsigned int key = 0u;
            if (w > 0.0f) {
                float nl = -__logf(u);                        // > 0 (u<1)
                float r  = __fdividef(fmaxf(w, 1e-30f), nl);  // > 0 finite
                key = __float_as_uint(r) | 0x80000000u;
            }
            mykeys[g * 4 + j] = key;
        }
    }
    __syncthreads();   // hist cleared, keys ready

    // ---- Phase 2: 4-pass radix-select of k-th largest key
    unsigned int prefixReg = 0u;
    int          kkReg     = 0;

    #pragma unroll
    for (int pass = 0; pass < 4; pass++) {
        const int shift = 24 - 8 * pass;

        if (pass == 0) {
            // Warp-aggregated atomics: one leader lane adds popc(peers) per
            // distinct digit -> ~3x fewer atomic lanes at the LSU.
            // Valid keys have bit31 set (digit >= 128); key==0 -> digit 0.
            #pragma unroll
            for (int j = 0; j < EPT; j++) {
                unsigned int d = mykeys[j] >> 24;
                unsigned int peers = __match_any_sync(FULLMASK, d);
                if (d != 0u && lane == (unsigned)(__ffs(peers) - 1))
                    atomicAdd(&hist[0][d], (unsigned int)__popc(peers));
            }
        } else {
            #pragma unroll
            for (int j = 0; j < EPT; j++) {
                unsigned int key = mykeys[j];
                if ((key ^ prefixReg) >> (shift + 8) == 0u)
                    atomicAdd(&hist[pass][(key >> shift) & 255u], 1u);
            }
        }
        __syncthreads();

        if (warp == 0) {
            // lane owns 8 consecutive bins; warp-local suffix sums
            unsigned int v[8], lsuf[8];
            #pragma unroll
            for (int i = 0; i < 8; i++) v[i] = hist[pass][lane * 8 + i];
            unsigned int tot = 0u;
            #pragma unroll
            for (int i = 7; i >= 0; i--) { tot += v[i]; lsuf[i] = tot; }

            unsigned int run = tot;
            #pragma unroll
            for (int off = 1; off < 32; off <<= 1) {
                unsigned int o = __shfl_down_sync(FULLMASK, run, off);
                if (lane + off < 32) run += o;
            }
            unsigned int above = run - tot;   // sum over lanes > lane

            int kkPass;
            if (pass == 0) {
                unsigned int cnt = __shfl_sync(FULLMASK, run, 0);   // total nonzero
                kkPass = (int)floorf(0.15f * (float)cnt);
                if (lane == 0 && kkPass <= 0) { s_prefix = 0xFFFFFFFFu; s_kk = 0; }
            } else {
                kkPass = kkReg;
            }

            if (kkPass > 0) {
                #pragma unroll
                for (int i = 0; i < 8; i++) {
                    unsigned int suf = lsuf[i] + above;   // count(byte >= bin)
                    unsigned int cgt = suf - v[i];        // count(byte >  bin)
                    if ((int)cgt < kkPass && kkPass <= (int)suf) {
                        s_prefix = prefixReg | ((unsigned int)(lane * 8 + i) << shift);
                        s_kk     = kkPass - (int)cgt;
                    }
                }
            }
        }
        __syncthreads();
        prefixReg = s_prefix;
        kkReg     = s_kk;
    }

    const unsigned int T = prefixReg;   // k-th largest key (0xFFFFFFFF if k==0)
    const int need_eq    = kkReg;       // # of key==T to take, lowest index first

    // ---- Phase 3: stable tie-break — exclusive scan of (key==T) counts
    int myEq = 0;
    #pragma unroll
    for (int j = 0; j < EPT; j++) myEq += (mykeys[j] == T) ? 1 : 0;

    int incl = myEq;
    #pragma unroll
    for (int off = 1; off < 32; off <<= 1) {
        int o = __shfl_up_sync(FULLMASK, incl, off);
        if (lane >= off) incl += o;
    }
    if (lane == 31) s_warpsum[warp] = incl;
    __syncthreads();
    int woff = 0;
    #pragma unroll
    for (int w = 0; w < 16; w++)
        woff += (w < warp) ? s_warpsum[w] : 0;
    int running = woff + (incl - myEq);

    // ---- Phase 4: selection + outputs (32-bit addressing)
    float4* o_ids = reinterpret_cast<float4*>(out + base);
    float4* o_m   = reinterpret_cast<float4*>(out + N + base);
    float4* o_nm  = reinterpret_cast<float4*>(out + 2 * N + base);

    #pragma unroll
    for (int g = 0; g < 2; g++) {
        int4 iv4 = reinterpret_cast<const int4*>(irow)[t * 2 + g];
        float oid[4], om[4], onm[4];
        #pragma unroll
        for (int j = 0; j < 4; j++) {
            int iv = (j == 0) ? iv4.x : (j == 1) ? iv4.y : (j == 2) ? iv4.z : iv4.w;
            unsigned int key = mykeys[g * 4 + j];
            bool sel = false;
            if (key > T) sel = true;
            else if (key == T) { sel = (running < need_eq); running++; }
            oid[j] = sel ? MASK_ID_F : (float)iv;
            om[j]  = sel ? 1.0f : 0.0f;
            onm[j] = sel ? -1.0f : -0.0f;
        }
        o_ids[t * 2 + g] = make_float4(oid[0], oid[1], oid[2], oid[3]);
        o_m  [t * 2 + g] = make_float4(om[0],  om[1],  om[2],  om[3]);
        o_nm [t * 2 + g] = make_float4(onm[0], onm[1], onm[2], onm[3]);
    }
}

extern "C" void kernel_launch(void* const* d_in, const int* in_sizes, int n_in,
                              void* d_out, int out_size)
{
    const int*   ids  = (const int*)d_in[0];
    const float* msk2 = (const float*)d_in[1];
    const float* u    = (const float*)d_in[2];
    float*       out  = (float*)d_out;

    const int N    = in_sizes[0];
    const int rows = N / ROW_LEN;

    gumbel_topk_mask_kernel<<<rows, THREADS>>>(ids, msk2, u, out, N);
}

// round 16
// speedup vs baseline: 1.1199x; 1.1199x over previous
#include <cuda_runtime.h>
#include <math.h>

// B=32, J=16, L=4096, MU_P=0.15, MASK_ID=103
#define ROW_LEN   4096
#define THREADS   512
#define EPT       8
#define MASK_ID_F 103.0f
#define FULLMASK  0xFFFFFFFFu

__global__ void __launch_bounds__(THREADS, 4)
gumbel_topk_mask_kernel(const int*   __restrict__ ids,
                        const float* __restrict__ msk2,   // (rows, 2*L)
                        const float* __restrict__ uu,     // (rows, L)
                        float*       __restrict__ out,    // (3, rows, L)
                        int N)
{
    __shared__ unsigned int hist[3][256];    // passes 0..2, cleared once (3KB)
    __shared__ unsigned int s_list[ROW_LEN]; // compacted candidates (worst case)
    __shared__ unsigned int s_n;
    __shared__ unsigned int s_prefix;
    __shared__ int          s_kk;
    __shared__ int          s_warpsum[16];

    const int t    = threadIdx.x;
    const int lane = t & 31;
    const int warp = t >> 5;
    const int row  = blockIdx.x;
    const int base = row * ROW_LEN;          // fits int

    const float* wrow = msk2 + row * (2 * ROW_LEN);
    const float* urow = uu   + base;
    const int*   irow = ids  + base;

    // Clear 3 histograms (768 words) + counter
    ((unsigned int*)hist)[t] = 0u;
    if (t < 256) ((unsigned int*)hist)[t + THREADS] = 0u;
    if (t == 0) s_n = 0u;

    // ---- Phase 1: build sortable keys.
    // order(score) == order( max(w,1e-30) / (-log2 u) )  (log2 = log/ln2 > 0
    // scale, order-preserving). r>0 so bits(r)|0x80000000 is order-preserving.
    // key==0 marks excluded (w<=0).
    unsigned int mykeys[EPT];
    #pragma unroll
    for (int g = 0; g < 2; g++) {
        float4 w4 = reinterpret_cast<const float4*>(wrow)[t * 2 + g];
        float4 u4 = reinterpret_cast<const float4*>(urow)[t * 2 + g];
        #pragma unroll
        for (int j = 0; j < 4; j++) {
            float w = (j == 0) ? w4.x : (j == 1) ? w4.y : (j == 2) ? w4.z : w4.w;
            float u = (j == 0) ? u4.x : (j == 1) ? u4.y : (j == 2) ? u4.z : u4.w;
            unsigned int key = 0u;
            if (w > 0.0f) {
                float nl = -__log2f(u);                       // > 0 (u<1)
                float r  = __fdividef(fmaxf(w, 1e-30f), nl);  // > 0 finite
                key = __float_as_uint(r) | 0x80000000u;
            }
            mykeys[g * 4 + j] = key;
        }
    }
    __syncthreads();   // clears done, keys ready

    // ---- Phase 2: 3 radix passes -> exact top-24-bit prefix
    unsigned int prefixReg = 0u;
    int          kkReg     = 0;

    #pragma unroll
    for (int pass = 0; pass < 3; pass++) {
        const int shift = 24 - 8 * pass;

        if (pass == 0) {
            #pragma unroll
            for (int j = 0; j < EPT; j++) {
                unsigned int key = mykeys[j];
                if (key != 0u) atomicAdd(&hist[0][key >> 24], 1u);
            }
        } else {
            #pragma unroll
            for (int j = 0; j < EPT; j++) {
                unsigned int key = mykeys[j];
                if ((key ^ prefixReg) >> (shift + 8) == 0u)
                    atomicAdd(&hist[pass][(key >> shift) & 255u], 1u);
            }
        }
        __syncthreads();

        if (warp == 0) {
            // lane owns 8 consecutive bins; warp-local suffix sums
            unsigned int v[8], lsuf[8];
            #pragma unroll
            for (int i = 0; i < 8; i++) v[i] = hist[pass][lane * 8 + i];
            unsigned int tot = 0u;
            #pragma unroll
            for (int i = 7; i >= 0; i--) { tot += v[i]; lsuf[i] = tot; }

            unsigned int run = tot;
            #pragma unroll
            for (int off = 1; off < 32; off <<= 1) {
                unsigned int o = __shfl_down_sync(FULLMASK, run, off);
                if (lane + off < 32) run += o;
            }
            unsigned int above = run - tot;   // sum over lanes > lane

            int kkPass;
            if (pass == 0) {
                unsigned int cnt = __shfl_sync(FULLMASK, run, 0);   // total nonzero
                kkPass = (int)floorf(0.15f * (float)cnt);
                if (lane == 0 && kkPass <= 0) { s_prefix = 0xFFFFFFFFu; s_kk = 0; }
            } else {
                kkPass = kkReg;
            }

            if (kkPass > 0) {
                #pragma unroll
                for (int i = 0; i < 8; i++) {
                    unsigned int suf = lsuf[i] + above;   // count(byte >= bin)
                    unsigned int cgt = suf - v[i];        // count(byte >  bin)
                    if ((int)cgt < kkPass && kkPass <= (int)suf) {
                        s_prefix = prefixReg | ((unsigned int)(lane * 8 + i) << shift);
                        s_kk     = kkPass - (int)cgt;
                    }
                }
            }
        }
        __syncthreads();
        prefixReg = s_prefix;
        kkReg     = s_kk;
    }

    // ---- Phase 2b: compact keys matching the 24-bit prefix (typically 1-3)
    if (kkReg > 0) {
        #pragma unroll
        for (int j = 0; j < EPT; j++) {
            unsigned int key = mykeys[j];
            if ((key & 0xFFFFFF00u) == prefixReg) {
                unsigned int idx = atomicAdd(&s_n, 1u);
                s_list[idx] = key;
            }
        }
    }
    __syncthreads();

    // ---- Phase 2c: warp 0 finds the kk-th largest among n tiny candidates.
    // Exact for any input (worst case slow, never wrong).
    if (warp == 0 && kkReg > 0) {
        int n = (int)s_n;
        int remaining = kkReg;
        unsigned int limit = 0xFFFFFFFFu;   // all keys < 0xFFFFFFFF
        for (;;) {
            unsigned int M = 0u;
            for (int i = lane; i < n; i += 32) {
                unsigned int x = s_list[i];
                if (x < limit) M = max(M, x);
            }
            #pragma unroll
            for (int off = 16; off; off >>= 1)
                M = max(M, __shfl_xor_sync(FULLMASK, M, off));
            int c = 0;
            for (int i = lane; i < n; i += 32)
                c += (s_list[i] == M) ? 1 : 0;
            #pragma unroll
            for (int off = 16; off; off >>= 1)
                c += __shfl_xor_sync(FULLMASK, c, off);
            if (remaining <= c) {
                if (lane == 0) { s_prefix = M; s_kk = remaining; }
                break;
            }
            remaining -= c;
            limit = M;
        }
    }
    __syncthreads();

    const unsigned int T = s_prefix;    // exact k-th largest key
    const int need_eq    = s_kk;        // # of key==T to take, lowest index first

    // ---- Phase 3: stable tie-break — exclusive scan of (key==T) counts
    int myEq = 0;
    #pragma unroll
    for (int j = 0; j < EPT; j++) myEq += (mykeys[j] == T) ? 1 : 0;

    int incl = myEq;
    #pragma unroll
    for (int off = 1; off < 32; off <<= 1) {
        int o = __shfl_up_sync(FULLMASK, incl, off);
        if (lane >= off) incl += o;
    }
    if (lane == 31) s_warpsum[warp] = incl;
    __syncthreads();
    int woff = 0;
    #pragma unroll
    for (int w = 0; w < 16; w++)
        woff += (w < warp) ? s_warpsum[w] : 0;
    int running = woff + (incl - myEq);

    // ---- Phase 4: selection + outputs (32-bit addressing)
    float4* o_ids = reinterpret_cast<float4*>(out + base);
    float4* o_m   = reinterpret_cast<float4*>(out + N + base);
    float4* o_nm  = reinterpret_cast<float4*>(out + 2 * N + base);

    #pragma unroll
    for (int g = 0; g < 2; g++) {
        int4 iv4 = reinterpret_cast<const int4*>(irow)[t * 2 + g];
        float oid[4], om[4], onm[4];
        #pragma unroll
        for (int j = 0; j < 4; j++) {
            int iv = (j == 0) ? iv4.x : (j == 1) ? iv4.y : (j == 2) ? iv4.z : iv4.w;
            unsigned int key = mykeys[g * 4 + j];
            bool sel = false;
            if (key > T) sel = true;
            else if (key == T) { sel = (running < need_eq); running++; }
            oid[j] = sel ? MASK_ID_F : (float)iv;
            om[j]  = sel ? 1.0f : 0.0f;
            onm[j] = sel ? -1.0f : -0.0f;
        }
        o_ids[t * 2 + g] = make_float4(oid[0], oid[1], oid[2], oid[3]);
        o_m  [t * 2 + g] = make_float4(om[0],  om[1],  om[2],  om[3]);
        o_nm [t * 2 + g] = make_float4(onm[0], onm[1], onm[2], onm[3]);
    }
}

extern "C" void kernel_launch(void* const* d_in, const int* in_sizes, int n_in,
                              void* d_out, int out_size)
{
    const int*   ids  = (const int*)d_in[0];
    const float* msk2 = (const float*)d_in[1];
    const float* u    = (const float*)d_in[2];
    float*       out  = (float*)d_out;

    const int N    = in_sizes[0];
    const int rows = N / ROW_LEN;

    gumbel_topk_mask_kernel<<<rows, THREADS>>>(ids, msk2, u, out, N);
}

// round 17
// speedup vs baseline: 1.1218x; 1.0017x over previous
#include <cuda_runtime.h>
#include <math.h>

// B=32, J=16, L=4096, MU_P=0.15, MASK_ID=103
#define ROW_LEN   4096
#define THREADS   512
#define EPT       8
#define MASK_ID_F 103.0f
#define FULLMASK  0xFFFFFFFFu

__global__ void __launch_bounds__(THREADS, 4)
gumbel_topk_mask_kernel(const int*   __restrict__ ids,
                        const float* __restrict__ msk2,   // (rows, 2*L)
                        const float* __restrict__ uu,     // (rows, L)
                        float*       __restrict__ out,    // (3, rows, L)
                        int N)
{
    __shared__ unsigned int hist[3][256];    // passes 0..2 (3KB), cleared once
    __shared__ unsigned int s_list[ROW_LEN]; // packed (lowByte,invIdx) candidates
    __shared__ unsigned int s_n;
    __shared__ unsigned int s_prefix;
    __shared__ int          s_kk;
    __shared__ unsigned int s_V;             // composite group threshold

    const int t    = threadIdx.x;
    const int lane = t & 31;
    const int warp = t >> 5;
    const int row  = blockIdx.x;
    const int base = row * ROW_LEN;          // fits int

    const float* wrow = msk2 + row * (2 * ROW_LEN);
    const float* urow = uu   + base;
    const int*   irow = ids  + base;

    // Clear 3 histograms (768 words) + counter
    ((unsigned int*)hist)[t] = 0u;
    if (t < 256) ((unsigned int*)hist)[t + THREADS] = 0u;
    if (t == 0) { s_n = 0u; s_V = 0u; }

    // ---- Phase 1: build sortable keys.
    // order(score) == order( max(w,1e-30) / (-log2 u) ); r>0 so
    // bits(r)|0x80000000 is order-preserving. key==0 marks excluded (w<=0).
    unsigned int mykeys[EPT];
    #pragma unroll
    for (int g = 0; g < 2; g++) {
        float4 w4 = reinterpret_cast<const float4*>(wrow)[t * 2 + g];
        float4 u4 = reinterpret_cast<const float4*>(urow)[t * 2 + g];
        #pragma unroll
        for (int j = 0; j < 4; j++) {
            float w = (j == 0) ? w4.x : (j == 1) ? w4.y : (j == 2) ? w4.z : w4.w;
            float u = (j == 0) ? u4.x : (j == 1) ? u4.y : (j == 2) ? u4.z : u4.w;
            unsigned int key = 0u;
            if (w > 0.0f) {
                float nl = -__log2f(u);                       // > 0 (u<1)
                float r  = __fdividef(fmaxf(w, 1e-30f), nl);  // > 0 finite
                key = __float_as_uint(r) | 0x80000000u;
            }
            mykeys[g * 4 + j] = key;
        }
    }
    __syncthreads();   // clears done, keys ready

    // ---- Phase 2: 3 radix passes -> exact top-24-bit prefix (bits [31:8])
    unsigned int prefixReg = 0u;
    int          kkReg     = 0;

    #pragma unroll
    for (int pass = 0; pass < 3; pass++) {
        const int shift = 24 - 8 * pass;

        if (pass == 0) {
            #pragma unroll
            for (int j = 0; j < EPT; j++) {
                unsigned int key = mykeys[j];
                if (key != 0u) atomicAdd(&hist[0][key >> 24], 1u);
            }
        } else {
            #pragma unroll
            for (int j = 0; j < EPT; j++) {
                unsigned int key = mykeys[j];
                if ((key ^ prefixReg) >> (shift + 8) == 0u)
                    atomicAdd(&hist[pass][(key >> shift) & 255u], 1u);
            }
        }
        __syncthreads();

        if (warp == 0) {
            // lane owns 8 consecutive bins; warp-local suffix sums
            unsigned int v[8], lsuf[8];
            #pragma unroll
            for (int i = 0; i < 8; i++) v[i] = hist[pass][lane * 8 + i];
            unsigned int tot = 0u;
            #pragma unroll
            for (int i = 7; i >= 0; i--) { tot += v[i]; lsuf[i] = tot; }

            unsigned int run = tot;
            #pragma unroll
            for (int off = 1; off < 32; off <<= 1) {
                unsigned int o = __shfl_down_sync(FULLMASK, run, off);
                if (lane + off < 32) run += o;
            }
            unsigned int above = run - tot;   // sum over lanes > lane

            int kkPass;
            if (pass == 0) {
                unsigned int cnt = __shfl_sync(FULLMASK, run, 0);   // total nonzero
                kkPass = (int)floorf(0.15f * (float)cnt);
                if (lane == 0 && kkPass <= 0) { s_prefix = 0xFFFFFFFFu; s_kk = 0; }
            } else {
                kkPass = kkReg;
            }

            if (kkPass > 0) {
                #pragma unroll
                for (int i = 0; i < 8; i++) {
                    unsigned int suf = lsuf[i] + above;   // count(byte >= bin)
                    unsigned int cgt = suf - v[i];        // count(byte >  bin)
                    if ((int)cgt < kkPass && kkPass <= (int)suf) {
                        s_prefix = prefixReg | ((unsigned int)(lane * 8 + i) << shift);
                        s_kk     = kkPass - (int)cgt;
                    }
                }
            }
        }
        __syncthreads();
        prefixReg = s_prefix;
        kkReg     = s_kk;
    }

    // ---- Phase 2b: compact candidates matching the 24-bit prefix.
    // Pack (lowByte, 4095-idx) -> 20 bits; ordering = (key asc, idx desc),
    // so "largest composite" = (key desc broken by idx asc) as required.
    if (kkReg > 0) {
        #pragma unroll
        for (int j = 0; j < EPT; j++) {
            unsigned int key = mykeys[j];
            if ((key & 0xFFFFFF00u) == prefixReg) {
                unsigned int eidx = (unsigned int)(t * EPT + j);
                unsigned int v20  = ((key & 0xFFu) << 12) | (4095u - eidx);
                unsigned int idx  = atomicAdd(&s_n, 1u);
                s_list[idx] = v20;
            }
        }
    }
    __syncthreads();

    // ---- Phase 2c: warp 0 extracts the kk-th largest composite (all distinct).
    if (warp == 0 && kkReg > 0) {
        int n = (int)s_n;
        int remaining = kkReg;
        unsigned int limit = 0xFFFFFFFFu;
        for (;;) {
            unsigned int M = 0u;
            for (int i = lane; i < n; i += 32) {
                unsigned int x = s_list[i];
                if (x < limit) M = max(M, x);
            }
            #pragma unroll
            for (int off = 16; off; off >>= 1)
                M = max(M, __shfl_xor_sync(FULLMASK, M, off));
            if (--remaining == 0) {
                if (lane == 0) s_V = M;      // kk-th largest composite
                break;
            }
            limit = M;
        }
    }
    __syncthreads();

    const unsigned int P = prefixReg;   // 24-bit prefix region (low byte 0)
    const unsigned int V = s_V;         // composite threshold within group

    // ---- Phase 4: branch-free selection + outputs (no tie-break scan!)
    float4* o_ids = reinterpret_cast<float4*>(out + base);
    float4* o_m   = reinterpret_cast<float4*>(out + N + base);
    float4* o_nm  = reinterpret_cast<float4*>(out + 2 * N + base);

    #pragma unroll
    for (int g = 0; g < 2; g++) {
        int4 iv4 = reinterpret_cast<const int4*>(irow)[t * 2 + g];
        float oid[4], om[4], onm[4];
        #pragma unroll
        for (int j = 0; j < 4; j++) {
            int iv = (j == 0) ? iv4.x : (j == 1) ? iv4.y : (j == 2) ? iv4.z : iv4.w;
            unsigned int key   = mykeys[g * 4 + j];
            unsigned int keyHi = key & 0xFFFFFF00u;
            unsigned int eidx  = (unsigned int)(t * EPT + g * 4 + j);
            unsigned int v20   = ((key & 0xFFu) << 12) | (4095u - eidx);
            bool sel = (keyHi > P) || (keyHi == P && v20 >= V);
            oid[j] = sel ? MASK_ID_F : (float)iv;
            om[j]  = sel ? 1.0f : 0.0f;
            onm[j] = sel ? -1.0f : -0.0f;
        }
        o_ids[t * 2 + g] = make_float4(oid[0], oid[1], oid[2], oid[3]);
        o_m  [t * 2 + g] = make_float4(om[0],  om[1],  om[2],  om[3]);
        o_nm [t * 2 + g] = make_float4(onm[0], onm[1], onm[2], onm[3]);
    }
}

extern "C" void kernel_launch(void* const* d_in, const int* in_sizes, int n_in,
                              void* d_out, int out_size)
{
    const int*   ids  = (const int*)d_in[0];
    const float* msk2 = (const float*)d_in[1];
    const float* u    = (const float*)d_in[2];
    float*       out  = (float*)d_out;

    const int N    = in_sizes[0];
    const int rows = N / ROW_LEN;

    gumbel_topk_mask_kernel<<<rows, THREADS>>>(ids, msk2, u, out, N);
}